// round 14
// baseline (speedup 1.0000x reference)
#include <cuda_runtime.h>
#include <cstdint>

// ---------------------------------------------------------------------------
// GIN (2 layers) on GB300 — CSR-gather aggregation + fused 2-GEMM MLP kernels.
// f32x2 (FFMA2) microkernels, register splat-packing, BK=16 cp.async W
// streaming (51KB smem -> 4 CTAs/SM), As/T1 aliasing.
// ---------------------------------------------------------------------------

#define NMAX 50000
#define EMAX 800000
#define CIN  64
#define CHID 128
#define SCAN_BS 1024
#define MAXPART 256

__device__ float g_h1pre[NMAX * CIN];
__device__ float g_h    [NMAX * CHID];
__device__ float g_h2pre[NMAX * CHID];

__device__ int g_deg   [NMAX];
__device__ int g_offs  [NMAX + 1];
__device__ int g_cursor[NMAX];
__device__ int g_csr   [EMAX];
__device__ int g_part  [MAXPART];
__device__ unsigned g_is64;

// ======================= small PTX helpers =================================
__device__ __forceinline__ uint32_t smem_u32(const void* p) {
    uint32_t a;
    asm("{ .reg .u64 t; cvta.to.shared.u64 t, %1; cvt.u32.u64 %0, t; }"
        : "=r"(a) : "l"(p));
    return a;
}
#define FMA2(acc_, a_, b_) \
    asm("fma.rn.f32x2 %0, %1, %2, %0;" : "+l"(acc_) : "l"(a_), "l"(b_))
#define PACK2(dst_, v_) \
    asm("mov.b64 %0, {%1, %1};" : "=l"(dst_) : "r"(__float_as_uint(v_)))
#define UNPK(lo_, hi_, p_) \
    asm("mov.b64 {%0, %1}, %2;" : "=r"(lo_), "=r"(hi_) : "l"(p_))
#define CP_WAIT0() asm volatile("cp.async.wait_group 0;" ::: "memory")
#define CP_WAIT1() asm volatile("cp.async.wait_group 1;" ::: "memory")

// Stream one 16-row W block (16 x CO floats) into smem via cp.async.
template <int CO>
__device__ __forceinline__ void prefetch_w(uint32_t wb_dst, const float* __restrict__ Wsrc,
                                           int kb, int tid) {
    constexpr int IT = (16 * CO / 4 + 255) / 256;   // 2 (CO=128) or 1 (CO=64)
    const float* base = Wsrc + (long long)kb * 16 * CO;
#pragma unroll
    for (int t = 0; t < IT; ++t) {
        int idx = tid + t * 256;
        if (16 * CO / 4 % 256 != 0 && idx >= 16 * CO / 4) break;
        int row = idx / (CO / 4);
        int c4  = idx % (CO / 4);
        uint32_t dst = wb_dst + (uint32_t)(row * CO + c4 * 4) * 4u;
        const float* src = base + row * CO + c4 * 4;
        asm volatile("cp.async.cg.shared.global [%0], [%1], 16;" :: "r"(dst), "l"(src));
    }
    asm volatile("cp.async.commit_group;" ::: "memory");
}

// ======================= CSR build =========================================
__global__ void detect_zero_kernel(const unsigned* __restrict__ ei_u32,
                                   int* __restrict__ deg, int N) {
    int i = blockIdx.x * blockDim.x + threadIdx.x;
    if (i < N) deg[i] = 0;
    if (blockIdx.x == gridDim.x - 1 && threadIdx.x < 32) {
        unsigned acc = 0;
#pragma unroll
        for (int t = 0; t < 16; ++t)
            acc |= ei_u32[2 * (threadIdx.x + t * 32) + 1];
#pragma unroll
        for (int o = 16; o > 0; o >>= 1)
            acc |= __shfl_down_sync(0xffffffffu, acc, o);
        if (threadIdx.x == 0) g_is64 = (acc == 0u) ? 1u : 0u;
    }
}
// 4 edges per thread.
__global__ void hist_kernel(const void* __restrict__ ei, int* __restrict__ deg, int E) {
    int e0 = (blockIdx.x * blockDim.x + threadIdx.x) * 4;
    if (e0 >= E) return;
    int n = min(4, E - e0);
    if (g_is64) {
        const long long* p = (const long long*)ei + E;
        for (int u = 0; u < n; ++u) atomicAdd(&deg[(int)p[e0 + u]], 1);
    } else {
        const int* p = (const int*)ei + E;
        for (int u = 0; u < n; ++u) atomicAdd(&deg[p[e0 + u]], 1);
    }
}
__global__ void scan1_kernel(const int* __restrict__ deg, int* __restrict__ offs,
                             int* __restrict__ part, int N) {
    __shared__ int wsum[32];
    const int tid = threadIdx.x, lane = tid & 31, wid = tid >> 5;
    int i = blockIdx.x * SCAN_BS + tid;
    int v = (i < N) ? deg[i] : 0;
    int x = v;
#pragma unroll
    for (int o = 1; o < 32; o <<= 1) {
        int y = __shfl_up_sync(0xffffffffu, x, o);
        if (lane >= o) x += y;
    }
    if (lane == 31) wsum[wid] = x;
    __syncthreads();
    if (wid == 0) {
        int w = wsum[lane];
#pragma unroll
        for (int o = 1; o < 32; o <<= 1) {
            int y = __shfl_up_sync(0xffffffffu, w, o);
            if (lane >= o) w += y;
        }
        wsum[lane] = w;
    }
    __syncthreads();
    int warpoff = (wid > 0) ? wsum[wid - 1] : 0;
    if (i < N) offs[i] = warpoff + x - v;
    if (tid == SCAN_BS - 1) part[blockIdx.x] = warpoff + x;
}
__global__ void scan23_kernel(int* __restrict__ offs, int* __restrict__ cursor,
                              const int* __restrict__ part, int nblk, int N) {
    __shared__ int soff;
    const int tid = threadIdx.x;
    if (tid < 32) {
        int s = 0;
        for (int j = tid; j < nblk; j += 32)
            if (j < (int)blockIdx.x) s += part[j];
#pragma unroll
        for (int o = 16; o > 0; o >>= 1) s += __shfl_down_sync(0xffffffffu, s, o);
        if (tid == 0) soff = s;
    }
    __syncthreads();
    int i = blockIdx.x * SCAN_BS + tid;
    if (i < N) {
        int v = offs[i] + soff;
        offs[i] = v;
        cursor[i] = v;
    }
    if (blockIdx.x == gridDim.x - 1 && tid < 32) {
        int s = 0;
        for (int j = tid; j < nblk; j += 32) s += part[j];
#pragma unroll
        for (int o = 16; o > 0; o >>= 1) s += __shfl_down_sync(0xffffffffu, s, o);
        if (tid == 0) offs[N] = s;
    }
}
// 4 edges per thread.
__global__ void fill_kernel(const void* __restrict__ ei, int* __restrict__ cursor,
                            int* __restrict__ csr, int E) {
    int e0 = (blockIdx.x * blockDim.x + threadIdx.x) * 4;
    if (e0 >= E) return;
    int n = min(4, E - e0);
    if (g_is64) {
        const long long* p = (const long long*)ei;
        for (int u = 0; u < n; ++u) {
            int s = (int)p[e0 + u];
            int d = (int)p[E + e0 + u];
            csr[atomicAdd(&cursor[d], 1)] = s;
        }
    } else {
        const int* p = (const int*)ei;
        for (int u = 0; u < n; ++u) {
            int s = p[e0 + u];
            int d = p[E + e0 + u];
            csr[atomicAdd(&cursor[d], 1)] = s;
        }
    }
}

// ======================= gathers ===========================================
__global__ void gather64_kernel(const float* __restrict__ feat,
                                const int* __restrict__ offs,
                                const int* __restrict__ csr,
                                float* __restrict__ out, int N) {
    int t = blockIdx.x * blockDim.x + threadIdx.x;
    int node = t >> 4;
    int lane = threadIdx.x & 15;
    if (node >= N) return;
    int s = offs[node], e = offs[node + 1];
    const float4* f4 = (const float4*)feat;
    float4 acc = f4[(long long)node * 16 + lane];
    int k = s;
    for (; k + 7 < e; k += 8) {
        int j[8];
#pragma unroll
        for (int u = 0; u < 8; ++u) j[u] = __ldg(&csr[k + u]);
        float4 v[8];
#pragma unroll
        for (int u = 0; u < 8; ++u) v[u] = f4[(long long)j[u] * 16 + lane];
#pragma unroll
        for (int u = 0; u < 8; ++u) {
            acc.x += v[u].x; acc.y += v[u].y; acc.z += v[u].z; acc.w += v[u].w;
        }
    }
    for (; k < e; ++k) {
        int j = __ldg(&csr[k]);
        float4 v = f4[(long long)j * 16 + lane];
        acc.x += v.x; acc.y += v.y; acc.z += v.z; acc.w += v.w;
    }
    ((float4*)out)[(long long)node * 16 + lane] = acc;
}
__global__ void gather128_kernel(const float* __restrict__ feat,
                                 const int* __restrict__ offs,
                                 const int* __restrict__ csr,
                                 float* __restrict__ out, int N) {
    int node = (int)((blockIdx.x * blockDim.x + threadIdx.x) >> 5);
    int lane = threadIdx.x & 31;
    if (node >= N) return;
    int s = offs[node], e = offs[node + 1];
    const float4* f4 = (const float4*)feat;
    float4 acc = f4[(long long)node * 32 + lane];
    int k = s;
    for (; k + 7 < e; k += 8) {
        int j[8];
#pragma unroll
        for (int u = 0; u < 8; ++u) j[u] = __ldg(&csr[k + u]);
        float4 v[8];
#pragma unroll
        for (int u = 0; u < 8; ++u) v[u] = f4[(long long)j[u] * 32 + lane];
#pragma unroll
        for (int u = 0; u < 8; ++u) {
            acc.x += v[u].x; acc.y += v[u].y; acc.z += v[u].z; acc.w += v[u].w;
        }
    }
    for (; k < e; ++k) {
        int j = __ldg(&csr[k]);
        float4 v = f4[(long long)j * 32 + lane];
        acc.x += v.x; acc.y += v.y; acc.z += v.z; acc.w += v.w;
    }
    ((float4*)out)[(long long)node * 32 + lane] = acc;
}

// ======================= fused 2-GEMM MLP ==================================
// Out[N,CO2] = act2(relu(A[N,CI] @ W1[CI,128] + b1) @ W2[128,CO2] + b2)
// Unsplatted k-major tiles (stride 68); register splat via mov.b64.
// BK=16 W double buffer (16KB) -> 51KB smem -> 4 CTAs/SM.
template <int CI, int CO2, int RELU2>
__global__ void __launch_bounds__(256, 4)
mlp_fused_kernel(const float* __restrict__ A,
                 const float* __restrict__ W1, const float* __restrict__ b1,
                 const float* __restrict__ W2, const float* __restrict__ b2,
                 float* __restrict__ Out, int Nrows) {
    constexpr int SA  = 68;            // row stride (floats), 16B-aligned
    constexpr int KB1 = CI / 16;       // stage-1 k-blocks (4 or 8)
    constexpr int KB2 = 128 / 16;      // stage-2 k-blocks (8)
    constexpr int NG  = CO2 / 64;

    extern __shared__ float sm[];
    float* As = sm;                    // CI x SA   (aliases T1)
    float* T1 = sm;                    // 128 x SA
    float* Wb = sm + 128 * SA;         // 2 x 16 x 128 W double buffer
    const uint32_t wb_addr = smem_u32(Wb);
    constexpr uint32_t WBUF_BYTES = 16 * 128 * 4;

    const int tid = threadIdx.x;
    const int tr  = tid >> 4;
    const int tc  = tid & 15;
    const long long rowBase = (long long)blockIdx.x * 64;

    prefetch_w<128>(wb_addr, W1, 0, tid);

    // ---- load A tile, transpose into As (k-major, unsplatted) ----
    constexpr int QA = CI / 4;
#pragma unroll
    for (int t = 0; t < 64 * QA / 256; ++t) {
        int idx = tid + t * 256;
        int m = idx / QA, q = idx % QA;
        long long row = rowBase + m;
        float4 v = make_float4(0.f, 0.f, 0.f, 0.f);
        if (row < Nrows) v = ((const float4*)(A + row * CI))[q];
        As[(q * 4 + 0) * SA + m] = v.x;
        As[(q * 4 + 1) * SA + m] = v.y;
        As[(q * 4 + 2) * SA + m] = v.z;
        As[(q * 4 + 3) * SA + m] = v.w;
    }
    prefetch_w<128>(wb_addr + WBUF_BYTES, W1, 1, tid);

    unsigned long long acc[4][4];
#pragma unroll
    for (int i = 0; i < 4; ++i)
#pragma unroll
        for (int j = 0; j < 4; ++j) acc[i][j] = 0ull;

    // ---------------- stage 1: acc = A @ W1 ----------------
#pragma unroll
    for (int kb = 0; kb < KB1; ++kb) {
        if (kb == KB1 - 1) { CP_WAIT0(); } else { CP_WAIT1(); }
        __syncthreads();
        const float* Bs  = Wb + (kb & 1) * (16 * 128);
        const float* Asb = As + kb * 16 * SA;
#pragma unroll
        for (int k = 0; k < 16; ++k) {
            float4 av = *(const float4*)&Asb[k * SA + tr * 4];
            unsigned long long ap0, ap1, ap2, ap3;
            PACK2(ap0, av.x); PACK2(ap1, av.y);
            PACK2(ap2, av.z); PACK2(ap3, av.w);
            ulonglong2 b0 = *(const ulonglong2*)&Bs[k * 128 + tc * 4];
            ulonglong2 b1v = *(const ulonglong2*)&Bs[k * 128 + 64 + tc * 4];
            FMA2(acc[0][0], ap0, b0.x); FMA2(acc[0][1], ap0, b0.y);
            FMA2(acc[0][2], ap0, b1v.x); FMA2(acc[0][3], ap0, b1v.y);
            FMA2(acc[1][0], ap1, b0.x); FMA2(acc[1][1], ap1, b0.y);
            FMA2(acc[1][2], ap1, b1v.x); FMA2(acc[1][3], ap1, b1v.y);
            FMA2(acc[2][0], ap2, b0.x); FMA2(acc[2][1], ap2, b0.y);
            FMA2(acc[2][2], ap2, b1v.x); FMA2(acc[2][3], ap2, b1v.y);
            FMA2(acc[3][0], ap3, b0.x); FMA2(acc[3][1], ap3, b0.y);
            FMA2(acc[3][2], ap3, b1v.x); FMA2(acc[3][3], ap3, b1v.y);
        }
        __syncthreads();   // buffer kb&1 free; As reads done (T1 alias ok)
        if (kb + 2 < KB1) prefetch_w<128>(wb_addr + (kb & 1) * WBUF_BYTES, W1, kb + 2, tid);
    }

    // First two W2 blocks stream while the stage-1 epilogue runs.
    prefetch_w<CO2>(wb_addr, W2, 0, tid);
    prefetch_w<CO2>(wb_addr + WBUF_BYTES, W2, 1, tid);

    // ---- stage-1 epilogue: bias + relu into T1 (aliasing As) ----
    {
        float bb[8];
#pragma unroll
        for (int e = 0; e < 4; ++e) {
            bb[e]     = __ldg(&b1[tc * 4 + e]);
            bb[4 + e] = __ldg(&b1[64 + tc * 4 + e]);
        }
#pragma unroll
        for (int i = 0; i < 4; ++i) {
            int m = tr * 4 + i;
#pragma unroll
            for (int g = 0; g < 2; ++g)
#pragma unroll
                for (int jp = 0; jp < 2; ++jp) {
                    uint32_t lo, hi;
                    UNPK(lo, hi, acc[i][g * 2 + jp]);
                    float v0 = fmaxf(__uint_as_float(lo) + bb[g * 4 + jp * 2 + 0], 0.f);
                    float v1 = fmaxf(__uint_as_float(hi) + bb[g * 4 + jp * 2 + 1], 0.f);
                    int c = g * 64 + tc * 4 + jp * 2;
                    T1[(c + 0) * SA + m] = v0;
                    T1[(c + 1) * SA + m] = v1;
                }
        }
    }
    __syncthreads();

    // ---------------- stage 2: out = T1 @ W2 ----------------
    unsigned long long acc2[4][2 * NG];
#pragma unroll
    for (int i = 0; i < 4; ++i)
#pragma unroll
        for (int j = 0; j < 2 * NG; ++j) acc2[i][j] = 0ull;

#pragma unroll
    for (int kb = 0; kb < KB2; ++kb) {
        if (kb == KB2 - 1) { CP_WAIT0(); } else { CP_WAIT1(); }
        __syncthreads();
        const float* Bs = Wb + (kb & 1) * (16 * 128);
        const float* Tb = T1 + kb * 16 * SA;
#pragma unroll
        for (int k = 0; k < 16; ++k) {
            float4 av = *(const float4*)&Tb[k * SA + tr * 4];
            unsigned long long ap0, ap1, ap2, ap3;
            PACK2(ap0, av.x); PACK2(ap1, av.y);
            PACK2(ap2, av.z); PACK2(ap3, av.w);
            ulonglong2 b0 = *(const ulonglong2*)&Bs[k * CO2 + tc * 4];
            FMA2(acc2[0][0], ap0, b0.x); FMA2(acc2[0][1], ap0, b0.y);
            FMA2(acc2[1][0], ap1, b0.x); FMA2(acc2[1][1], ap1, b0.y);
            FMA2(acc2[2][0], ap2, b0.x); FMA2(acc2[2][1], ap2, b0.y);
            FMA2(acc2[3][0], ap3, b0.x); FMA2(acc2[3][1], ap3, b0.y);
            if (NG == 2) {
                ulonglong2 b1v = *(const ulonglong2*)&Bs[k * CO2 + 64 + tc * 4];
                FMA2(acc2[0][2], ap0, b1v.x); FMA2(acc2[0][3], ap0, b1v.y);
                FMA2(acc2[1][2], ap1, b1v.x); FMA2(acc2[1][3], ap1, b1v.y);
                FMA2(acc2[2][2], ap2, b1v.x); FMA2(acc2[2][3], ap2, b1v.y);
                FMA2(acc2[3][2], ap3, b1v.x); FMA2(acc2[3][3], ap3, b1v.y);
            }
        }
        __syncthreads();
        if (kb + 2 < KB2) prefetch_w<CO2>(wb_addr + (kb & 1) * WBUF_BYTES, W2, kb + 2, tid);
    }

    // ---- final epilogue ----
    {
        float bb[4 * NG];
#pragma unroll
        for (int g = 0; g < NG; ++g)
#pragma unroll
            for (int e = 0; e < 4; ++e)
                bb[g * 4 + e] = __ldg(&b2[g * 64 + tc * 4 + e]);
#pragma unroll
        for (int i = 0; i < 4; ++i) {
            long long row = rowBase + tr * 4 + i;
            if (row >= Nrows) continue;
#pragma unroll
            for (int g = 0; g < NG; ++g) {
                uint32_t l0, h0, l1, h1;
                UNPK(l0, h0, acc2[i][g * 2 + 0]);
                UNPK(l1, h1, acc2[i][g * 2 + 1]);
                float4 o;
                o.x = __uint_as_float(l0) + bb[g * 4 + 0];
                o.y = __uint_as_float(h0) + bb[g * 4 + 1];
                o.z = __uint_as_float(l1) + bb[g * 4 + 2];
                o.w = __uint_as_float(h1) + bb[g * 4 + 3];
                if (RELU2) {
                    o.x = fmaxf(o.x, 0.f); o.y = fmaxf(o.y, 0.f);
                    o.z = fmaxf(o.z, 0.f); o.w = fmaxf(o.w, 0.f);
                }
                *(float4*)(Out + row * CO2 + g * 64 + tc * 4) = o;
            }
        }
    }
}

// ---------------------------------------------------------------------------
extern "C" void kernel_launch(void* const* d_in, const int* in_sizes, int n_in,
                              void* d_out, int out_size) {
    const float* x  = (const float*)d_in[0];
    const void*  ei = d_in[1];
    const float* W1 = (const float*)d_in[2];
    const float* b1 = (const float*)d_in[3];
    const float* W2 = (const float*)d_in[4];
    const float* b2 = (const float*)d_in[5];
    const float* W3 = (const float*)d_in[6];
    const float* b3 = (const float*)d_in[7];
    const float* W4 = (const float*)d_in[8];
    const float* b4 = (const float*)d_in[9];

    const int N = in_sizes[0] / CIN;
    const int E = in_sizes[1] / 2;

    float *h1pre, *h, *h2pre;
    cudaGetSymbolAddress((void**)&h1pre, g_h1pre);
    cudaGetSymbolAddress((void**)&h,     g_h);
    cudaGetSymbolAddress((void**)&h2pre, g_h2pre);
    int *deg, *offs, *cursor, *csr, *part;
    cudaGetSymbolAddress((void**)&deg,    g_deg);
    cudaGetSymbolAddress((void**)&offs,   g_offs);
    cudaGetSymbolAddress((void**)&cursor, g_cursor);
    cudaGetSymbolAddress((void**)&csr,    g_csr);
    cudaGetSymbolAddress((void**)&part,   g_part);

    float* out = (float*)d_out;
    const int rtiles      = (N + 63) / 64;
    const int edge4_blocks = (E + 1023) / 1024;   // 4 edges per thread
    const int scan_blocks = (N + SCAN_BS - 1) / SCAN_BS;
    const int g64_blocks  = (N * 16 + 255) / 256;
    const int g128_blocks = (N * 32 + 255) / 256;

    // Unsplatted As/T1 (128 x 68 floats) + BK=16 W double buffer -> 51.2KB.
    const int smem_mlp = (128 * 68 + 2 * 16 * 128) * 4;
    cudaFuncSetAttribute(mlp_fused_kernel<CIN,  CHID, 1>,
                         cudaFuncAttributeMaxDynamicSharedMemorySize, smem_mlp);
    cudaFuncSetAttribute(mlp_fused_kernel<CHID, CIN,  0>,
                         cudaFuncAttributeMaxDynamicSharedMemorySize, smem_mlp);

    // ---- CSR build (5 launches) ----
    detect_zero_kernel<<<(N + 255) / 256, 256>>>((const unsigned*)ei, deg, N);
    hist_kernel<<<edge4_blocks, 256>>>(ei, deg, E);
    scan1_kernel<<<scan_blocks, SCAN_BS>>>(deg, offs, part, N);
    scan23_kernel<<<scan_blocks, SCAN_BS>>>(offs, cursor, part, scan_blocks, N);
    fill_kernel<<<edge4_blocks, 256>>>(ei, cursor, csr, E);

    // ---- Layer 1 ----
    gather64_kernel<<<g64_blocks, 256>>>(x, offs, csr, h1pre, N);
    mlp_fused_kernel<CIN,  CHID, 1><<<rtiles, 256, smem_mlp>>>(h1pre, W1, b1, W2, b2, h, N);

    // ---- Layer 2 ----
    gather128_kernel<<<g128_blocks, 256>>>(h, offs, csr, h2pre, N);
    mlp_fused_kernel<CHID, CIN,  0><<<rtiles, 256, smem_mlp>>>(h2pre, W3, b3, W4, b4, out, N);
}

// round 15
// speedup vs baseline: 1.0064x; 1.0064x over previous
#include <cuda_runtime.h>
#include <cstdint>

// ---------------------------------------------------------------------------
// GIN (2 layers) on GB300 — CSR-gather aggregation + fused 2-GEMM MLP kernels.
// f32x2 (FFMA2) microkernels with register splat-packing (unsplatted SMEM
// tiles -> 66KB -> 3 CTAs/SM), BK=32 cp.async W pipeline, As/T1 aliasing.
// CSR hist/fill process 4 edges/thread.
// ---------------------------------------------------------------------------

#define NMAX 50000
#define EMAX 800000
#define CIN  64
#define CHID 128
#define SCAN_BS 1024
#define MAXPART 256

__device__ float g_h1pre[NMAX * CIN];
__device__ float g_h    [NMAX * CHID];
__device__ float g_h2pre[NMAX * CHID];

__device__ int g_deg   [NMAX];
__device__ int g_offs  [NMAX + 1];
__device__ int g_cursor[NMAX];
__device__ int g_csr   [EMAX];
__device__ int g_part  [MAXPART];
__device__ unsigned g_is64;

// ======================= small PTX helpers =================================
__device__ __forceinline__ uint32_t smem_u32(const void* p) {
    uint32_t a;
    asm("{ .reg .u64 t; cvta.to.shared.u64 t, %1; cvt.u32.u64 %0, t; }"
        : "=r"(a) : "l"(p));
    return a;
}
#define FMA2(acc_, a_, b_) \
    asm("fma.rn.f32x2 %0, %1, %2, %0;" : "+l"(acc_) : "l"(a_), "l"(b_))
#define PACK2(dst_, v_) \
    asm("mov.b64 %0, {%1, %1};" : "=l"(dst_) : "r"(__float_as_uint(v_)))
#define UNPK(lo_, hi_, p_) \
    asm("mov.b64 {%0, %1}, %2;" : "=r"(lo_), "=r"(hi_) : "l"(p_))
#define CP_WAIT0() asm volatile("cp.async.wait_group 0;" ::: "memory")
#define CP_WAIT1() asm volatile("cp.async.wait_group 1;" ::: "memory")

// Stream one 32-row W block (32 x CO floats) into smem via cp.async.
template <int CO>
__device__ __forceinline__ void prefetch_w(uint32_t wb_dst, const float* __restrict__ Wsrc,
                                           int kb, int tid) {
    constexpr int IT = (32 * CO / 4) / 256;
    const float* base = Wsrc + (long long)kb * 32 * CO;
#pragma unroll
    for (int t = 0; t < IT; ++t) {
        int idx = tid + t * 256;
        int row = idx / (CO / 4);
        int c4  = idx % (CO / 4);
        uint32_t dst = wb_dst + (uint32_t)(row * CO + c4 * 4) * 4u;
        const float* src = base + row * CO + c4 * 4;
        asm volatile("cp.async.cg.shared.global [%0], [%1], 16;" :: "r"(dst), "l"(src));
    }
    asm volatile("cp.async.commit_group;" ::: "memory");
}

// ======================= CSR build =========================================
__global__ void detect_zero_kernel(const unsigned* __restrict__ ei_u32,
                                   int* __restrict__ deg, int N) {
    int i = blockIdx.x * blockDim.x + threadIdx.x;
    if (i < N) deg[i] = 0;
    if (blockIdx.x == gridDim.x - 1 && threadIdx.x < 32) {
        unsigned acc = 0;
#pragma unroll
        for (int t = 0; t < 16; ++t)
            acc |= ei_u32[2 * (threadIdx.x + t * 32) + 1];
#pragma unroll
        for (int o = 16; o > 0; o >>= 1)
            acc |= __shfl_down_sync(0xffffffffu, acc, o);
        if (threadIdx.x == 0) g_is64 = (acc == 0u) ? 1u : 0u;
    }
}
// 4 edges per thread.
__global__ void hist_kernel(const void* __restrict__ ei, int* __restrict__ deg, int E) {
    int e0 = (blockIdx.x * blockDim.x + threadIdx.x) * 4;
    if (e0 >= E) return;
    int n = min(4, E - e0);
    if (g_is64) {
        const long long* p = (const long long*)ei + E;
        for (int u = 0; u < n; ++u) atomicAdd(&deg[(int)p[e0 + u]], 1);
    } else {
        const int* p = (const int*)ei + E;
        for (int u = 0; u < n; ++u) atomicAdd(&deg[p[e0 + u]], 1);
    }
}
__global__ void scan1_kernel(const int* __restrict__ deg, int* __restrict__ offs,
                             int* __restrict__ part, int N) {
    __shared__ int wsum[32];
    const int tid = threadIdx.x, lane = tid & 31, wid = tid >> 5;
    int i = blockIdx.x * SCAN_BS + tid;
    int v = (i < N) ? deg[i] : 0;
    int x = v;
#pragma unroll
    for (int o = 1; o < 32; o <<= 1) {
        int y = __shfl_up_sync(0xffffffffu, x, o);
        if (lane >= o) x += y;
    }
    if (lane == 31) wsum[wid] = x;
    __syncthreads();
    if (wid == 0) {
        int w = wsum[lane];
#pragma unroll
        for (int o = 1; o < 32; o <<= 1) {
            int y = __shfl_up_sync(0xffffffffu, w, o);
            if (lane >= o) w += y;
        }
        wsum[lane] = w;
    }
    __syncthreads();
    int warpoff = (wid > 0) ? wsum[wid - 1] : 0;
    if (i < N) offs[i] = warpoff + x - v;
    if (tid == SCAN_BS - 1) part[blockIdx.x] = warpoff + x;
}
__global__ void scan23_kernel(int* __restrict__ offs, int* __restrict__ cursor,
                              const int* __restrict__ part, int nblk, int N) {
    __shared__ int soff;
    const int tid = threadIdx.x;
    if (tid < 32) {
        int s = 0;
        for (int j = tid; j < nblk; j += 32)
            if (j < (int)blockIdx.x) s += part[j];
#pragma unroll
        for (int o = 16; o > 0; o >>= 1) s += __shfl_down_sync(0xffffffffu, s, o);
        if (tid == 0) soff = s;
    }
    __syncthreads();
    int i = blockIdx.x * SCAN_BS + tid;
    if (i < N) {
        int v = offs[i] + soff;
        offs[i] = v;
        cursor[i] = v;
    }
    if (blockIdx.x == gridDim.x - 1 && tid < 32) {
        int s = 0;
        for (int j = tid; j < nblk; j += 32) s += part[j];
#pragma unroll
        for (int o = 16; o > 0; o >>= 1) s += __shfl_down_sync(0xffffffffu, s, o);
        if (tid == 0) offs[N] = s;
    }
}
// 4 edges per thread.
__global__ void fill_kernel(const void* __restrict__ ei, int* __restrict__ cursor,
                            int* __restrict__ csr, int E) {
    int e0 = (blockIdx.x * blockDim.x + threadIdx.x) * 4;
    if (e0 >= E) return;
    int n = min(4, E - e0);
    if (g_is64) {
        const long long* p = (const long long*)ei;
        for (int u = 0; u < n; ++u) {
            int s = (int)p[e0 + u];
            int d = (int)p[E + e0 + u];
            csr[atomicAdd(&cursor[d], 1)] = s;
        }
    } else {
        const int* p = (const int*)ei;
        for (int u = 0; u < n; ++u) {
            int s = p[e0 + u];
            int d = p[E + e0 + u];
            csr[atomicAdd(&cursor[d], 1)] = s;
        }
    }
}

// ======================= gathers ===========================================
__global__ void gather64_kernel(const float* __restrict__ feat,
                                const int* __restrict__ offs,
                                const int* __restrict__ csr,
                                float* __restrict__ out, int N) {
    int t = blockIdx.x * blockDim.x + threadIdx.x;
    int node = t >> 4;
    int lane = threadIdx.x & 15;
    if (node >= N) return;
    int s = offs[node], e = offs[node + 1];
    const float4* f4 = (const float4*)feat;
    float4 acc = f4[(long long)node * 16 + lane];
    int k = s;
    for (; k + 7 < e; k += 8) {
        int j[8];
#pragma unroll
        for (int u = 0; u < 8; ++u) j[u] = __ldg(&csr[k + u]);
        float4 v[8];
#pragma unroll
        for (int u = 0; u < 8; ++u) v[u] = f4[(long long)j[u] * 16 + lane];
#pragma unroll
        for (int u = 0; u < 8; ++u) {
            acc.x += v[u].x; acc.y += v[u].y; acc.z += v[u].z; acc.w += v[u].w;
        }
    }
    for (; k < e; ++k) {
        int j = __ldg(&csr[k]);
        float4 v = f4[(long long)j * 16 + lane];
        acc.x += v.x; acc.y += v.y; acc.z += v.z; acc.w += v.w;
    }
    ((float4*)out)[(long long)node * 16 + lane] = acc;
}
__global__ void gather128_kernel(const float* __restrict__ feat,
                                 const int* __restrict__ offs,
                                 const int* __restrict__ csr,
                                 float* __restrict__ out, int N) {
    int node = (int)((blockIdx.x * blockDim.x + threadIdx.x) >> 5);
    int lane = threadIdx.x & 31;
    if (node >= N) return;
    int s = offs[node], e = offs[node + 1];
    const float4* f4 = (const float4*)feat;
    float4 acc = f4[(long long)node * 32 + lane];
    int k = s;
    for (; k + 7 < e; k += 8) {
        int j[8];
#pragma unroll
        for (int u = 0; u < 8; ++u) j[u] = __ldg(&csr[k + u]);
        float4 v[8];
#pragma unroll
        for (int u = 0; u < 8; ++u) v[u] = f4[(long long)j[u] * 32 + lane];
#pragma unroll
        for (int u = 0; u < 8; ++u) {
            acc.x += v[u].x; acc.y += v[u].y; acc.z += v[u].z; acc.w += v[u].w;
        }
    }
    for (; k < e; ++k) {
        int j = __ldg(&csr[k]);
        float4 v = f4[(long long)j * 32 + lane];
        acc.x += v.x; acc.y += v.y; acc.z += v.z; acc.w += v.w;
    }
    ((float4*)out)[(long long)node * 32 + lane] = acc;
}

// ======================= fused 2-GEMM MLP ==================================
// Out[N,CO2] = act2(relu(A[N,CI] @ W1[CI,128] + b1) @ W2[128,CO2] + b2)
// Unsplatted k-major tiles (stride 68 floats); splat via mov.b64 in registers
// (idle issue slots — FMA2 rt binds). BK=32 W double buffer. 66KB -> 3 CTAs/SM.
template <int CI, int CO2, int RELU2>
__global__ void __launch_bounds__(256, 3)
mlp_fused_kernel(const float* __restrict__ A,
                 const float* __restrict__ W1, const float* __restrict__ b1,
                 const float* __restrict__ W2, const float* __restrict__ b2,
                 float* __restrict__ Out, int Nrows) {
    constexpr int SA  = 68;            // row stride (floats), 16B-aligned
    constexpr int KB1 = CI / 32;
    constexpr int KB2 = 128 / 32;
    constexpr int NG  = CO2 / 64;

    extern __shared__ float sm[];
    float* As = sm;                    // CI x SA   (aliases T1)
    float* T1 = sm;                    // 128 x SA
    float* Wb = sm + 128 * SA;         // 2 x 32 x 128 W double buffer
    const uint32_t wb_addr = smem_u32(Wb);
    constexpr uint32_t WBUF_BYTES = 32 * 128 * 4;

    const int tid = threadIdx.x;
    const int tr  = tid >> 4;
    const int tc  = tid & 15;
    const long long rowBase = (long long)blockIdx.x * 64;

    prefetch_w<128>(wb_addr, W1, 0, tid);

    // ---- load A tile, transpose into As (k-major, unsplatted) ----
    constexpr int QA = CI / 4;
#pragma unroll
    for (int t = 0; t < 64 * QA / 256; ++t) {
        int idx = tid + t * 256;
        int m = idx / QA, q = idx % QA;
        long long row = rowBase + m;
        float4 v = make_float4(0.f, 0.f, 0.f, 0.f);
        if (row < Nrows) v = ((const float4*)(A + row * CI))[q];
        As[(q * 4 + 0) * SA + m] = v.x;
        As[(q * 4 + 1) * SA + m] = v.y;
        As[(q * 4 + 2) * SA + m] = v.z;
        As[(q * 4 + 3) * SA + m] = v.w;
    }
    if (KB1 > 1) prefetch_w<128>(wb_addr + WBUF_BYTES, W1, 1, tid);

    unsigned long long acc[4][4];
#pragma unroll
    for (int i = 0; i < 4; ++i)
#pragma unroll
        for (int j = 0; j < 4; ++j) acc[i][j] = 0ull;

    // ---------------- stage 1: acc = A @ W1 ----------------
#pragma unroll
    for (int kb = 0; kb < KB1; ++kb) {
        if (kb == KB1 - 1) { CP_WAIT0(); } else { CP_WAIT1(); }
        __syncthreads();
        const float* Bs  = Wb + (kb & 1) * (32 * 128);
        const float* Asb = As + kb * 32 * SA;
#pragma unroll
        for (int k = 0; k < 32; ++k) {
            float4 av = *(const float4*)&Asb[k * SA + tr * 4];
            unsigned long long ap0, ap1, ap2, ap3;
            PACK2(ap0, av.x); PACK2(ap1, av.y);
            PACK2(ap2, av.z); PACK2(ap3, av.w);
            ulonglong2 b0 = *(const ulonglong2*)&Bs[k * 128 + tc * 4];
            ulonglong2 b1v = *(const ulonglong2*)&Bs[k * 128 + 64 + tc * 4];
            FMA2(acc[0][0], ap0, b0.x); FMA2(acc[0][1], ap0, b0.y);
            FMA2(acc[0][2], ap0, b1v.x); FMA2(acc[0][3], ap0, b1v.y);
            FMA2(acc[1][0], ap1, b0.x); FMA2(acc[1][1], ap1, b0.y);
            FMA2(acc[1][2], ap1, b1v.x); FMA2(acc[1][3], ap1, b1v.y);
            FMA2(acc[2][0], ap2, b0.x); FMA2(acc[2][1], ap2, b0.y);
            FMA2(acc[2][2], ap2, b1v.x); FMA2(acc[2][3], ap2, b1v.y);
            FMA2(acc[3][0], ap3, b0.x); FMA2(acc[3][1], ap3, b0.y);
            FMA2(acc[3][2], ap3, b1v.x); FMA2(acc[3][3], ap3, b1v.y);
        }
        __syncthreads();   // buffer kb&1 free; As reads done (T1 alias ok)
        if (kb + 2 < KB1) prefetch_w<128>(wb_addr + (kb & 1) * WBUF_BYTES, W1, kb + 2, tid);
    }

    // Both W2 blocks stream while the stage-1 epilogue runs.
    prefetch_w<CO2>(wb_addr, W2, 0, tid);
    prefetch_w<CO2>(wb_addr + WBUF_BYTES, W2, 1, tid);

    // ---- stage-1 epilogue: bias + relu into T1 (aliasing As) ----
    {
        float bb[8];
#pragma unroll
        for (int e = 0; e < 4; ++e) {
            bb[e]     = __ldg(&b1[tc * 4 + e]);
            bb[4 + e] = __ldg(&b1[64 + tc * 4 + e]);
        }
#pragma unroll
        for (int i = 0; i < 4; ++i) {
            int m = tr * 4 + i;
#pragma unroll
            for (int g = 0; g < 2; ++g)
#pragma unroll
                for (int jp = 0; jp < 2; ++jp) {
                    uint32_t lo, hi;
                    UNPK(lo, hi, acc[i][g * 2 + jp]);
                    float v0 = fmaxf(__uint_as_float(lo) + bb[g * 4 + jp * 2 + 0], 0.f);
                    float v1 = fmaxf(__uint_as_float(hi) + bb[g * 4 + jp * 2 + 1], 0.f);
                    int c = g * 64 + tc * 4 + jp * 2;
                    T1[(c + 0) * SA + m] = v0;
                    T1[(c + 1) * SA + m] = v1;
                }
        }
    }
    __syncthreads();

    // ---------------- stage 2: out = T1 @ W2 ----------------
    unsigned long long acc2[4][2 * NG];
#pragma unroll
    for (int i = 0; i < 4; ++i)
#pragma unroll
        for (int j = 0; j < 2 * NG; ++j) acc2[i][j] = 0ull;

#pragma unroll
    for (int kb = 0; kb < KB2; ++kb) {
        if (kb == KB2 - 1) { CP_WAIT0(); } else { CP_WAIT1(); }
        __syncthreads();
        const float* Bs = Wb + (kb & 1) * (32 * 128);
        const float* Tb = T1 + kb * 32 * SA;
#pragma unroll
        for (int k = 0; k < 32; ++k) {
            float4 av = *(const float4*)&Tb[k * SA + tr * 4];
            unsigned long long ap0, ap1, ap2, ap3;
            PACK2(ap0, av.x); PACK2(ap1, av.y);
            PACK2(ap2, av.z); PACK2(ap3, av.w);
            ulonglong2 b0 = *(const ulonglong2*)&Bs[k * CO2 + tc * 4];
            FMA2(acc2[0][0], ap0, b0.x); FMA2(acc2[0][1], ap0, b0.y);
            FMA2(acc2[1][0], ap1, b0.x); FMA2(acc2[1][1], ap1, b0.y);
            FMA2(acc2[2][0], ap2, b0.x); FMA2(acc2[2][1], ap2, b0.y);
            FMA2(acc2[3][0], ap3, b0.x); FMA2(acc2[3][1], ap3, b0.y);
            if (NG == 2) {
                ulonglong2 b1v = *(const ulonglong2*)&Bs[k * CO2 + 64 + tc * 4];
                FMA2(acc2[0][2], ap0, b1v.x); FMA2(acc2[0][3], ap0, b1v.y);
                FMA2(acc2[1][2], ap1, b1v.x); FMA2(acc2[1][3], ap1, b1v.y);
                FMA2(acc2[2][2], ap2, b1v.x); FMA2(acc2[2][3], ap2, b1v.y);
                FMA2(acc2[3][2], ap3, b1v.x); FMA2(acc2[3][3], ap3, b1v.y);
            }
        }
        __syncthreads();
        if (kb + 2 < KB2) prefetch_w<CO2>(wb_addr + (kb & 1) * WBUF_BYTES, W2, kb + 2, tid);
    }

    // ---- final epilogue ----
    {
        float bb[4 * NG];
#pragma unroll
        for (int g = 0; g < NG; ++g)
#pragma unroll
            for (int e = 0; e < 4; ++e)
                bb[g * 4 + e] = __ldg(&b2[g * 64 + tc * 4 + e]);
#pragma unroll
        for (int i = 0; i < 4; ++i) {
            long long row = rowBase + tr * 4 + i;
            if (row >= Nrows) continue;
#pragma unroll
            for (int g = 0; g < NG; ++g) {
                uint32_t l0, h0, l1, h1;
                UNPK(l0, h0, acc2[i][g * 2 + 0]);
                UNPK(l1, h1, acc2[i][g * 2 + 1]);
                float4 o;
                o.x = __uint_as_float(l0) + bb[g * 4 + 0];
                o.y = __uint_as_float(h0) + bb[g * 4 + 1];
                o.z = __uint_as_float(l1) + bb[g * 4 + 2];
                o.w = __uint_as_float(h1) + bb[g * 4 + 3];
                if (RELU2) {
                    o.x = fmaxf(o.x, 0.f); o.y = fmaxf(o.y, 0.f);
                    o.z = fmaxf(o.z, 0.f); o.w = fmaxf(o.w, 0.f);
                }
                *(float4*)(Out + row * CO2 + g * 64 + tc * 4) = o;
            }
        }
    }
}

// ---------------------------------------------------------------------------
extern "C" void kernel_launch(void* const* d_in, const int* in_sizes, int n_in,
                              void* d_out, int out_size) {
    const float* x  = (const float*)d_in[0];
    const void*  ei = d_in[1];
    const float* W1 = (const float*)d_in[2];
    const float* b1 = (const float*)d_in[3];
    const float* W2 = (const float*)d_in[4];
    const float* b2 = (const float*)d_in[5];
    const float* W3 = (const float*)d_in[6];
    const float* b3 = (const float*)d_in[7];
    const float* W4 = (const float*)d_in[8];
    const float* b4 = (const float*)d_in[9];

    const int N = in_sizes[0] / CIN;
    const int E = in_sizes[1] / 2;

    float *h1pre, *h, *h2pre;
    cudaGetSymbolAddress((void**)&h1pre, g_h1pre);
    cudaGetSymbolAddress((void**)&h,     g_h);
    cudaGetSymbolAddress((void**)&h2pre, g_h2pre);
    int *deg, *offs, *cursor, *csr, *part;
    cudaGetSymbolAddress((void**)&deg,    g_deg);
    cudaGetSymbolAddress((void**)&offs,   g_offs);
    cudaGetSymbolAddress((void**)&cursor, g_cursor);
    cudaGetSymbolAddress((void**)&csr,    g_csr);
    cudaGetSymbolAddress((void**)&part,   g_part);

    float* out = (float*)d_out;
    const int rtiles       = (N + 63) / 64;
    const int edge4_blocks = (E + 1023) / 1024;   // 4 edges per thread
    const int scan_blocks  = (N + SCAN_BS - 1) / SCAN_BS;
    const int g64_blocks   = (N * 16 + 255) / 256;
    const int g128_blocks  = (N * 32 + 255) / 256;

    // Unsplatted As/T1 (128 x 68 floats) + BK=32 W double buffer -> 66KB.
    const int smem_mlp = (128 * 68 + 2 * 32 * 128) * 4;
    cudaFuncSetAttribute(mlp_fused_kernel<CIN,  CHID, 1>,
                         cudaFuncAttributeMaxDynamicSharedMemorySize, smem_mlp);
    cudaFuncSetAttribute(mlp_fused_kernel<CHID, CIN,  0>,
                         cudaFuncAttributeMaxDynamicSharedMemorySize, smem_mlp);

    // ---- CSR build (5 launches) ----
    detect_zero_kernel<<<(N + 255) / 256, 256>>>((const unsigned*)ei, deg, N);
    hist_kernel<<<edge4_blocks, 256>>>(ei, deg, E);
    scan1_kernel<<<scan_blocks, SCAN_BS>>>(deg, offs, part, N);
    scan23_kernel<<<scan_blocks, SCAN_BS>>>(offs, cursor, part, scan_blocks, N);
    fill_kernel<<<edge4_blocks, 256>>>(ei, cursor, csr, E);

    // ---- Layer 1 ----
    gather64_kernel<<<g64_blocks, 256>>>(x, offs, csr, h1pre, N);
    mlp_fused_kernel<CIN,  CHID, 1><<<rtiles, 256, smem_mlp>>>(h1pre, W1, b1, W2, b2, h, N);

    // ---- Layer 2 ----
    gather128_kernel<<<g128_blocks, 256>>>(h, offs, csr, h2pre, N);
    mlp_fused_kernel<CHID, CIN,  0><<<rtiles, 256, smem_mlp>>>(h2pre, W3, b3, W4, b4, out, N);
}

// round 16
// speedup vs baseline: 1.0093x; 1.0028x over previous
#include <cuda_runtime.h>
#include <cstdint>

// ---------------------------------------------------------------------------
// GIN (2 layers) on GB300 — CSR-gather aggregation + fused 2-GEMM MLP kernels.
// f32x2 (FFMA2) microkernels with register splat-packing (unsplatted SMEM
// tiles -> 66KB -> 3 CTAs/SM), BK=32 cp.async W pipeline, As/T1 aliasing.
// CSR build: histogram + single-pass decoupled-lookback scan + fill.
// ---------------------------------------------------------------------------

#define NMAX 50000
#define EMAX 800000
#define CIN  64
#define CHID 128
#define SCAN_BS 1024
#define MAXPART 256

__device__ float g_h1pre[NMAX * CIN];
__device__ float g_h    [NMAX * CHID];
__device__ float g_h2pre[NMAX * CHID];

__device__ int g_deg   [NMAX];
__device__ int g_offs  [NMAX + 1];
__device__ int g_cursor[NMAX];
__device__ int g_csr   [EMAX];
__device__ unsigned long long g_scanstate[MAXPART];  // (flag<<32)|value
__device__ unsigned g_is64;

// ======================= small PTX helpers =================================
__device__ __forceinline__ uint32_t smem_u32(const void* p) {
    uint32_t a;
    asm("{ .reg .u64 t; cvta.to.shared.u64 t, %1; cvt.u32.u64 %0, t; }"
        : "=r"(a) : "l"(p));
    return a;
}
#define FMA2(acc_, a_, b_) \
    asm("fma.rn.f32x2 %0, %1, %2, %0;" : "+l"(acc_) : "l"(a_), "l"(b_))
#define PACK2(dst_, v_) \
    asm("mov.b64 %0, {%1, %1};" : "=l"(dst_) : "r"(__float_as_uint(v_)))
#define UNPK(lo_, hi_, p_) \
    asm("mov.b64 {%0, %1}, %2;" : "=r"(lo_), "=r"(hi_) : "l"(p_))
#define CP_WAIT0() asm volatile("cp.async.wait_group 0;" ::: "memory")
#define CP_WAIT1() asm volatile("cp.async.wait_group 1;" ::: "memory")

template <int CO>
__device__ __forceinline__ void prefetch_w(uint32_t wb_dst, const float* __restrict__ Wsrc,
                                           int kb, int tid) {
    constexpr int IT = (32 * CO / 4) / 256;
    const float* base = Wsrc + (long long)kb * 32 * CO;
#pragma unroll
    for (int t = 0; t < IT; ++t) {
        int idx = tid + t * 256;
        int row = idx / (CO / 4);
        int c4  = idx % (CO / 4);
        uint32_t dst = wb_dst + (uint32_t)(row * CO + c4 * 4) * 4u;
        const float* src = base + row * CO + c4 * 4;
        asm volatile("cp.async.cg.shared.global [%0], [%1], 16;" :: "r"(dst), "l"(src));
    }
    asm volatile("cp.async.commit_group;" ::: "memory");
}

// ======================= CSR build =========================================
// Zero deg + scan state; last block's warp 0 detects index dtype.
__global__ void detect_zero_kernel(const unsigned* __restrict__ ei_u32,
                                   int* __restrict__ deg, int N) {
    int i = blockIdx.x * blockDim.x + threadIdx.x;
    if (i < N) deg[i] = 0;
    if (blockIdx.x == 0 && threadIdx.x < MAXPART) g_scanstate[threadIdx.x] = 0ull;
    if (blockIdx.x == gridDim.x - 1 && threadIdx.x < 32) {
        unsigned acc = 0;
#pragma unroll
        for (int t = 0; t < 16; ++t)
            acc |= ei_u32[2 * (threadIdx.x + t * 32) + 1];
#pragma unroll
        for (int o = 16; o > 0; o >>= 1)
            acc |= __shfl_down_sync(0xffffffffu, acc, o);
        if (threadIdx.x == 0) g_is64 = (acc == 0u) ? 1u : 0u;
    }
}
__global__ void hist_kernel(const void* __restrict__ ei, int* __restrict__ deg, int E) {
    int e = blockIdx.x * blockDim.x + threadIdx.x;
    if (e >= E) return;
    int d = g_is64 ? (int)((const long long*)ei)[E + e] : ((const int*)ei)[E + e];
    atomicAdd(&deg[d], 1);
}
// Single-pass exclusive scan with decoupled lookback. All 49 blocks are
// co-resident (49 < 148 SMs) so spinning on predecessors cannot deadlock.
// Output values are timing-independent -> deterministic.
__global__ void scan_lookback_kernel(const int* __restrict__ deg,
                                     int* __restrict__ offs,
                                     int* __restrict__ cursor, int N) {
    __shared__ int wsum[32];
    __shared__ int s_excl;
    const int tid = threadIdx.x, lane = tid & 31, wid = tid >> 5;
    const int bid = blockIdx.x;
    int i = bid * SCAN_BS + tid;
    int v = (i < N) ? deg[i] : 0;
    int x = v;
#pragma unroll
    for (int o = 1; o < 32; o <<= 1) {
        int y = __shfl_up_sync(0xffffffffu, x, o);
        if (lane >= o) x += y;
    }
    if (lane == 31) wsum[wid] = x;
    __syncthreads();
    if (wid == 0) {
        int w = wsum[lane];
#pragma unroll
        for (int o = 1; o < 32; o <<= 1) {
            int y = __shfl_up_sync(0xffffffffu, w, o);
            if (lane >= o) w += y;
        }
        wsum[lane] = w;
    }
    __syncthreads();
    int warpoff = (wid > 0) ? wsum[wid - 1] : 0;
    int local_excl = warpoff + x - v;
    int total = wsum[31];

    if (tid == 0) {
        if (bid == 0) {
            atomicExch(&g_scanstate[0], (2ull << 32) | (unsigned)total);
            s_excl = 0;
        } else {
            atomicExch(&g_scanstate[bid], (1ull << 32) | (unsigned)total);
            int run = 0;
            int j = bid - 1;
            while (true) {
                unsigned long long st;
                do { st = atomicAdd(&g_scanstate[j], 0ull); } while ((st >> 32) == 0);
                run += (int)(unsigned)st;
                if ((st >> 32) == 2ull) break;
                --j;
            }
            atomicExch(&g_scanstate[bid], (2ull << 32) | (unsigned)(run + total));
            s_excl = run;
        }
    }
    __syncthreads();
    int excl = s_excl;
    if (i < N) {
        int val = local_excl + excl;
        offs[i] = val;
        cursor[i] = val;
    }
    if (bid == gridDim.x - 1 && tid == 0) offs[N] = excl + total;
}
__global__ void fill_kernel(const void* __restrict__ ei, int* __restrict__ cursor,
                            int* __restrict__ csr, int E) {
    int e = blockIdx.x * blockDim.x + threadIdx.x;
    if (e >= E) return;
    int s, d;
    if (g_is64) {
        const long long* p = (const long long*)ei;
        s = (int)p[e];
        d = (int)p[E + e];
    } else {
        const int* p = (const int*)ei;
        s = p[e];
        d = p[E + e];
    }
    int pos = atomicAdd(&cursor[d], 1);
    csr[pos] = s;
}

// ======================= gathers ===========================================
__global__ void gather64_kernel(const float* __restrict__ feat,
                                const int* __restrict__ offs,
                                const int* __restrict__ csr,
                                float* __restrict__ out, int N) {
    int t = blockIdx.x * blockDim.x + threadIdx.x;
    int node = t >> 4;
    int lane = threadIdx.x & 15;
    if (node >= N) return;
    int s = offs[node], e = offs[node + 1];
    const float4* f4 = (const float4*)feat;
    float4 acc = f4[(long long)node * 16 + lane];
    int k = s;
    for (; k + 7 < e; k += 8) {
        int j[8];
#pragma unroll
        for (int u = 0; u < 8; ++u) j[u] = __ldg(&csr[k + u]);
        float4 v[8];
#pragma unroll
        for (int u = 0; u < 8; ++u) v[u] = f4[(long long)j[u] * 16 + lane];
#pragma unroll
        for (int u = 0; u < 8; ++u) {
            acc.x += v[u].x; acc.y += v[u].y; acc.z += v[u].z; acc.w += v[u].w;
        }
    }
    for (; k < e; ++k) {
        int j = __ldg(&csr[k]);
        float4 v = f4[(long long)j * 16 + lane];
        acc.x += v.x; acc.y += v.y; acc.z += v.z; acc.w += v.w;
    }
    ((float4*)out)[(long long)node * 16 + lane] = acc;
}
__global__ void gather128_kernel(const float* __restrict__ feat,
                                 const int* __restrict__ offs,
                                 const int* __restrict__ csr,
                                 float* __restrict__ out, int N) {
    int node = (int)((blockIdx.x * blockDim.x + threadIdx.x) >> 5);
    int lane = threadIdx.x & 31;
    if (node >= N) return;
    int s = offs[node], e = offs[node + 1];
    const float4* f4 = (const float4*)feat;
    float4 acc = f4[(long long)node * 32 + lane];
    int k = s;
    for (; k + 7 < e; k += 8) {
        int j[8];
#pragma unroll
        for (int u = 0; u < 8; ++u) j[u] = __ldg(&csr[k + u]);
        float4 v[8];
#pragma unroll
        for (int u = 0; u < 8; ++u) v[u] = f4[(long long)j[u] * 32 + lane];
#pragma unroll
        for (int u = 0; u < 8; ++u) {
            acc.x += v[u].x; acc.y += v[u].y; acc.z += v[u].z; acc.w += v[u].w;
        }
    }
    for (; k < e; ++k) {
        int j = __ldg(&csr[k]);
        float4 v = f4[(long long)j * 32 + lane];
        acc.x += v.x; acc.y += v.y; acc.z += v.z; acc.w += v.w;
    }
    ((float4*)out)[(long long)node * 32 + lane] = acc;
}

// ======================= fused 2-GEMM MLP ==================================
// Out[N,CO2] = act2(relu(A[N,CI] @ W1[CI,128] + b1) @ W2[128,CO2] + b2)
// Unsplatted k-major tiles (stride 68); register splat via mov.b64 (idle
// slots — FMA2 rt binds). BK=32 W double buffer. 66KB smem -> 3 CTAs/SM.
template <int CI, int CO2, int RELU2>
__global__ void __launch_bounds__(256, 3)
mlp_fused_kernel(const float* __restrict__ A,
                 const float* __restrict__ W1, const float* __restrict__ b1,
                 const float* __restrict__ W2, const float* __restrict__ b2,
                 float* __restrict__ Out, int Nrows) {
    constexpr int SA  = 68;
    constexpr int KB1 = CI / 32;
    constexpr int KB2 = 128 / 32;
    constexpr int NG  = CO2 / 64;

    extern __shared__ float sm[];
    float* As = sm;                    // CI x SA   (aliases T1)
    float* T1 = sm;                    // 128 x SA
    float* Wb = sm + 128 * SA;         // 2 x 32 x 128 W double buffer
    const uint32_t wb_addr = smem_u32(Wb);
    constexpr uint32_t WBUF_BYTES = 32 * 128 * 4;

    const int tid = threadIdx.x;
    const int tr  = tid >> 4;
    const int tc  = tid & 15;
    const long long rowBase = (long long)blockIdx.x * 64;

    prefetch_w<128>(wb_addr, W1, 0, tid);

    constexpr int QA = CI / 4;
#pragma unroll
    for (int t = 0; t < 64 * QA / 256; ++t) {
        int idx = tid + t * 256;
        int m = idx / QA, q = idx % QA;
        long long row = rowBase + m;
        float4 v = make_float4(0.f, 0.f, 0.f, 0.f);
        if (row < Nrows) v = ((const float4*)(A + row * CI))[q];
        As[(q * 4 + 0) * SA + m] = v.x;
        As[(q * 4 + 1) * SA + m] = v.y;
        As[(q * 4 + 2) * SA + m] = v.z;
        As[(q * 4 + 3) * SA + m] = v.w;
    }
    if (KB1 > 1) prefetch_w<128>(wb_addr + WBUF_BYTES, W1, 1, tid);

    unsigned long long acc[4][4];
#pragma unroll
    for (int i = 0; i < 4; ++i)
#pragma unroll
        for (int j = 0; j < 4; ++j) acc[i][j] = 0ull;

    // ---------------- stage 1: acc = A @ W1 ----------------
#pragma unroll
    for (int kb = 0; kb < KB1; ++kb) {
        if (kb == KB1 - 1) { CP_WAIT0(); } else { CP_WAIT1(); }
        __syncthreads();
        const float* Bs  = Wb + (kb & 1) * (32 * 128);
        const float* Asb = As + kb * 32 * SA;
#pragma unroll
        for (int k = 0; k < 32; ++k) {
            float4 av = *(const float4*)&Asb[k * SA + tr * 4];
            unsigned long long ap0, ap1, ap2, ap3;
            PACK2(ap0, av.x); PACK2(ap1, av.y);
            PACK2(ap2, av.z); PACK2(ap3, av.w);
            ulonglong2 b0 = *(const ulonglong2*)&Bs[k * 128 + tc * 4];
            ulonglong2 b1v = *(const ulonglong2*)&Bs[k * 128 + 64 + tc * 4];
            FMA2(acc[0][0], ap0, b0.x); FMA2(acc[0][1], ap0, b0.y);
            FMA2(acc[0][2], ap0, b1v.x); FMA2(acc[0][3], ap0, b1v.y);
            FMA2(acc[1][0], ap1, b0.x); FMA2(acc[1][1], ap1, b0.y);
            FMA2(acc[1][2], ap1, b1v.x); FMA2(acc[1][3], ap1, b1v.y);
            FMA2(acc[2][0], ap2, b0.x); FMA2(acc[2][1], ap2, b0.y);
            FMA2(acc[2][2], ap2, b1v.x); FMA2(acc[2][3], ap2, b1v.y);
            FMA2(acc[3][0], ap3, b0.x); FMA2(acc[3][1], ap3, b0.y);
            FMA2(acc[3][2], ap3, b1v.x); FMA2(acc[3][3], ap3, b1v.y);
        }
        __syncthreads();
        if (kb + 2 < KB1) prefetch_w<128>(wb_addr + (kb & 1) * WBUF_BYTES, W1, kb + 2, tid);
    }

    prefetch_w<CO2>(wb_addr, W2, 0, tid);
    prefetch_w<CO2>(wb_addr + WBUF_BYTES, W2, 1, tid);

    // ---- stage-1 epilogue: bias + relu into T1 (aliasing As) ----
    {
        float bb[8];
#pragma unroll
        for (int e = 0; e < 4; ++e) {
            bb[e]     = __ldg(&b1[tc * 4 + e]);
            bb[4 + e] = __ldg(&b1[64 + tc * 4 + e]);
        }
#pragma unroll
        for (int i = 0; i < 4; ++i) {
            int m = tr * 4 + i;
#pragma unroll
            for (int g = 0; g < 2; ++g)
#pragma unroll
                for (int jp = 0; jp < 2; ++jp) {
                    uint32_t lo, hi;
                    UNPK(lo, hi, acc[i][g * 2 + jp]);
                    float v0 = fmaxf(__uint_as_float(lo) + bb[g * 4 + jp * 2 + 0], 0.f);
                    float v1 = fmaxf(__uint_as_float(hi) + bb[g * 4 + jp * 2 + 1], 0.f);
                    int c = g * 64 + tc * 4 + jp * 2;
                    T1[(c + 0) * SA + m] = v0;
                    T1[(c + 1) * SA + m] = v1;
                }
        }
    }
    __syncthreads();

    // ---------------- stage 2: out = T1 @ W2 ----------------
    unsigned long long acc2[4][2 * NG];
#pragma unroll
    for (int i = 0; i < 4; ++i)
#pragma unroll
        for (int j = 0; j < 2 * NG; ++j) acc2[i][j] = 0ull;

#pragma unroll
    for (int kb = 0; kb < KB2; ++kb) {
        if (kb == KB2 - 1) { CP_WAIT0(); } else { CP_WAIT1(); }
        __syncthreads();
        const float* Bs = Wb + (kb & 1) * (32 * 128);
        const float* Tb = T1 + kb * 32 * SA;
#pragma unroll
        for (int k = 0; k < 32; ++k) {
            float4 av = *(const float4*)&Tb[k * SA + tr * 4];
            unsigned long long ap0, ap1, ap2, ap3;
            PACK2(ap0, av.x); PACK2(ap1, av.y);
            PACK2(ap2, av.z); PACK2(ap3, av.w);
            ulonglong2 b0 = *(const ulonglong2*)&Bs[k * CO2 + tc * 4];
            FMA2(acc2[0][0], ap0, b0.x); FMA2(acc2[0][1], ap0, b0.y);
            FMA2(acc2[1][0], ap1, b0.x); FMA2(acc2[1][1], ap1, b0.y);
            FMA2(acc2[2][0], ap2, b0.x); FMA2(acc2[2][1], ap2, b0.y);
            FMA2(acc2[3][0], ap3, b0.x); FMA2(acc2[3][1], ap3, b0.y);
            if (NG == 2) {
                ulonglong2 b1v = *(const ulonglong2*)&Bs[k * CO2 + 64 + tc * 4];
                FMA2(acc2[0][2], ap0, b1v.x); FMA2(acc2[0][3], ap0, b1v.y);
                FMA2(acc2[1][2], ap1, b1v.x); FMA2(acc2[1][3], ap1, b1v.y);
                FMA2(acc2[2][2], ap2, b1v.x); FMA2(acc2[2][3], ap2, b1v.y);
                FMA2(acc2[3][2], ap3, b1v.x); FMA2(acc2[3][3], ap3, b1v.y);
            }
        }
        __syncthreads();
        if (kb + 2 < KB2) prefetch_w<CO2>(wb_addr + (kb & 1) * WBUF_BYTES, W2, kb + 2, tid);
    }

    // ---- final epilogue ----
    {
        float bb[4 * NG];
#pragma unroll
        for (int g = 0; g < NG; ++g)
#pragma unroll
            for (int e = 0; e < 4; ++e)
                bb[g * 4 + e] = __ldg(&b2[g * 64 + tc * 4 + e]);
#pragma unroll
        for (int i = 0; i < 4; ++i) {
            long long row = rowBase + tr * 4 + i;
            if (row >= Nrows) continue;
#pragma unroll
            for (int g = 0; g < NG; ++g) {
                uint32_t l0, h0, l1, h1;
                UNPK(l0, h0, acc2[i][g * 2 + 0]);
                UNPK(l1, h1, acc2[i][g * 2 + 1]);
                float4 o;
                o.x = __uint_as_float(l0) + bb[g * 4 + 0];
                o.y = __uint_as_float(h0) + bb[g * 4 + 1];
                o.z = __uint_as_float(l1) + bb[g * 4 + 2];
                o.w = __uint_as_float(h1) + bb[g * 4 + 3];
                if (RELU2) {
                    o.x = fmaxf(o.x, 0.f); o.y = fmaxf(o.y, 0.f);
                    o.z = fmaxf(o.z, 0.f); o.w = fmaxf(o.w, 0.f);
                }
                *(float4*)(Out + row * CO2 + g * 64 + tc * 4) = o;
            }
        }
    }
}

// ---------------------------------------------------------------------------
extern "C" void kernel_launch(void* const* d_in, const int* in_sizes, int n_in,
                              void* d_out, int out_size) {
    const float* x  = (const float*)d_in[0];
    const void*  ei = d_in[1];
    const float* W1 = (const float*)d_in[2];
    const float* b1 = (const float*)d_in[3];
    const float* W2 = (const float*)d_in[4];
    const float* b2 = (const float*)d_in[5];
    const float* W3 = (const float*)d_in[6];
    const float* b3 = (const float*)d_in[7];
    const float* W4 = (const float*)d_in[8];
    const float* b4 = (const float*)d_in[9];

    const int N = in_sizes[0] / CIN;
    const int E = in_sizes[1] / 2;

    float *h1pre, *h, *h2pre;
    cudaGetSymbolAddress((void**)&h1pre, g_h1pre);
    cudaGetSymbolAddress((void**)&h,     g_h);
    cudaGetSymbolAddress((void**)&h2pre, g_h2pre);
    int *deg, *offs, *cursor, *csr;
    cudaGetSymbolAddress((void**)&deg,    g_deg);
    cudaGetSymbolAddress((void**)&offs,   g_offs);
    cudaGetSymbolAddress((void**)&cursor, g_cursor);
    cudaGetSymbolAddress((void**)&csr,    g_csr);

    float* out = (float*)d_out;
    const int rtiles      = (N + 63) / 64;
    const int edge_blocks = (E + 255) / 256;
    const int scan_blocks = (N + SCAN_BS - 1) / SCAN_BS;   // 49 (< 148 SMs)
    const int g64_blocks  = (N * 16 + 255) / 256;
    const int g128_blocks = (N * 32 + 255) / 256;

    // Unsplatted As/T1 (128 x 68 floats) + BK=32 W double buffer -> 66KB.
    const int smem_mlp = (128 * 68 + 2 * 32 * 128) * 4;
    cudaFuncSetAttribute(mlp_fused_kernel<CIN,  CHID, 1>,
                         cudaFuncAttributeMaxDynamicSharedMemorySize, smem_mlp);
    cudaFuncSetAttribute(mlp_fused_kernel<CHID, CIN,  0>,
                         cudaFuncAttributeMaxDynamicSharedMemorySize, smem_mlp);

    // ---- CSR build (4 launches) ----
    detect_zero_kernel<<<(N + 255) / 256, 256>>>((const unsigned*)ei, deg, N);
    hist_kernel<<<edge_blocks, 256>>>(ei, deg, E);
    scan_lookback_kernel<<<scan_blocks, SCAN_BS>>>(deg, offs, cursor, N);
    fill_kernel<<<edge_blocks, 256>>>(ei, cursor, csr, E);

    // ---- Layer 1 ----
    gather64_kernel<<<g64_blocks, 256>>>(x, offs, csr, h1pre, N);
    mlp_fused_kernel<CIN,  CHID, 1><<<rtiles, 256, smem_mlp>>>(h1pre, W1, b1, W2, b2, h, N);

    // ---- Layer 2 ----
    gather128_kernel<<<g128_blocks, 256>>>(h, offs, csr, h2pre, N);
    mlp_fused_kernel<CHID, CIN,  0><<<rtiles, 256, smem_mlp>>>(h2pre, W3, b3, W4, b4, out, N);
}

// round 17
// speedup vs baseline: 1.0170x; 1.0076x over previous
#include <cuda_runtime.h>
#include <cstdint>

// ---------------------------------------------------------------------------
// GIN (2 layers) on GB300 — CSR-gather aggregation + fused 2-GEMM MLP kernels.
// f32x2 (FFMA2) microkernels with register splat-packing (unsplatted SMEM
// tiles -> 66KB -> 3 CTAs/SM), BK=32 cp.async W pipeline, As/T1 aliasing.
// CSR build: rank-capturing histogram + decoupled-lookback scan + atomic-free
// fill (csr[offs[d]+rank[e]] = src).
// ---------------------------------------------------------------------------

#define NMAX 50000
#define EMAX 800000
#define CIN  64
#define CHID 128
#define SCAN_BS 1024
#define MAXPART 256

__device__ float g_h1pre[NMAX * CIN];
__device__ float g_h    [NMAX * CHID];
__device__ float g_h2pre[NMAX * CHID];

__device__ int g_deg [NMAX];
__device__ int g_offs[NMAX + 1];
__device__ int g_csr [EMAX];
__device__ int g_rank[EMAX];
__device__ unsigned long long g_scanstate[MAXPART];  // (flag<<32)|value
__device__ unsigned g_is64;

// ======================= small PTX helpers =================================
__device__ __forceinline__ uint32_t smem_u32(const void* p) {
    uint32_t a;
    asm("{ .reg .u64 t; cvta.to.shared.u64 t, %1; cvt.u32.u64 %0, t; }"
        : "=r"(a) : "l"(p));
    return a;
}
#define FMA2(acc_, a_, b_) \
    asm("fma.rn.f32x2 %0, %1, %2, %0;" : "+l"(acc_) : "l"(a_), "l"(b_))
#define PACK2(dst_, v_) \
    asm("mov.b64 %0, {%1, %1};" : "=l"(dst_) : "r"(__float_as_uint(v_)))
#define UNPK(lo_, hi_, p_) \
    asm("mov.b64 {%0, %1}, %2;" : "=r"(lo_), "=r"(hi_) : "l"(p_))
#define CP_WAIT0() asm volatile("cp.async.wait_group 0;" ::: "memory")
#define CP_WAIT1() asm volatile("cp.async.wait_group 1;" ::: "memory")

template <int CO>
__device__ __forceinline__ void prefetch_w(uint32_t wb_dst, const float* __restrict__ Wsrc,
                                           int kb, int tid) {
    constexpr int IT = (32 * CO / 4) / 256;
    const float* base = Wsrc + (long long)kb * 32 * CO;
#pragma unroll
    for (int t = 0; t < IT; ++t) {
        int idx = tid + t * 256;
        int row = idx / (CO / 4);
        int c4  = idx % (CO / 4);
        uint32_t dst = wb_dst + (uint32_t)(row * CO + c4 * 4) * 4u;
        const float* src = base + row * CO + c4 * 4;
        asm volatile("cp.async.cg.shared.global [%0], [%1], 16;" :: "r"(dst), "l"(src));
    }
    asm volatile("cp.async.commit_group;" ::: "memory");
}

// ======================= CSR build =========================================
__global__ void detect_zero_kernel(const unsigned* __restrict__ ei_u32,
                                   int* __restrict__ deg, int N) {
    int i = blockIdx.x * blockDim.x + threadIdx.x;
    if (i < N) deg[i] = 0;
    if (blockIdx.x == 0 && threadIdx.x < MAXPART) g_scanstate[threadIdx.x] = 0ull;
    if (blockIdx.x == gridDim.x - 1 && threadIdx.x < 32) {
        unsigned acc = 0;
#pragma unroll
        for (int t = 0; t < 16; ++t)
            acc |= ei_u32[2 * (threadIdx.x + t * 32) + 1];
#pragma unroll
        for (int o = 16; o > 0; o >>= 1)
            acc |= __shfl_down_sync(0xffffffffu, acc, o);
        if (threadIdx.x == 0) g_is64 = (acc == 0u) ? 1u : 0u;
    }
}
// Histogram that also captures each edge's rank within its destination.
__global__ void hist_kernel(const void* __restrict__ ei, int* __restrict__ deg,
                            int* __restrict__ rank, int E) {
    int e = blockIdx.x * blockDim.x + threadIdx.x;
    if (e >= E) return;
    int d = g_is64 ? (int)((const long long*)ei)[E + e] : ((const int*)ei)[E + e];
    rank[e] = atomicAdd(&deg[d], 1);
}
// Single-pass exclusive scan with decoupled lookback (49 blocks < 148 SMs:
// all co-resident, no deadlock; values timing-independent -> deterministic).
__global__ void scan_lookback_kernel(const int* __restrict__ deg,
                                     int* __restrict__ offs, int N) {
    __shared__ int wsum[32];
    __shared__ int s_excl;
    const int tid = threadIdx.x, lane = tid & 31, wid = tid >> 5;
    const int bid = blockIdx.x;
    int i = bid * SCAN_BS + tid;
    int v = (i < N) ? deg[i] : 0;
    int x = v;
#pragma unroll
    for (int o = 1; o < 32; o <<= 1) {
        int y = __shfl_up_sync(0xffffffffu, x, o);
        if (lane >= o) x += y;
    }
    if (lane == 31) wsum[wid] = x;
    __syncthreads();
    if (wid == 0) {
        int w = wsum[lane];
#pragma unroll
        for (int o = 1; o < 32; o <<= 1) {
            int y = __shfl_up_sync(0xffffffffu, w, o);
            if (lane >= o) w += y;
        }
        wsum[lane] = w;
    }
    __syncthreads();
    int warpoff = (wid > 0) ? wsum[wid - 1] : 0;
    int local_excl = warpoff + x - v;
    int total = wsum[31];

    if (tid == 0) {
        if (bid == 0) {
            atomicExch(&g_scanstate[0], (2ull << 32) | (unsigned)total);
            s_excl = 0;
        } else {
            atomicExch(&g_scanstate[bid], (1ull << 32) | (unsigned)total);
            int run = 0;
            int j = bid - 1;
            while (true) {
                unsigned long long st;
                do { st = atomicAdd(&g_scanstate[j], 0ull); } while ((st >> 32) == 0);
                run += (int)(unsigned)st;
                if ((st >> 32) == 2ull) break;
                --j;
            }
            atomicExch(&g_scanstate[bid], (2ull << 32) | (unsigned)(run + total));
            s_excl = run;
        }
    }
    __syncthreads();
    int excl = s_excl;
    if (i < N) offs[i] = local_excl + excl;
    if (bid == gridDim.x - 1 && tid == 0) offs[N] = excl + total;
}
// Atomic-free fill: position = offs[dst] + rank[edge].
__global__ void fill_kernel(const void* __restrict__ ei,
                            const int* __restrict__ offs,
                            const int* __restrict__ rank,
                            int* __restrict__ csr, int E) {
    int e = blockIdx.x * blockDim.x + threadIdx.x;
    if (e >= E) return;
    int s, d;
    if (g_is64) {
        const long long* p = (const long long*)ei;
        s = (int)p[e];
        d = (int)p[E + e];
    } else {
        const int* p = (const int*)ei;
        s = p[e];
        d = p[E + e];
    }
    csr[offs[d] + rank[e]] = s;
}

// ======================= gathers ===========================================
__global__ void gather64_kernel(const float* __restrict__ feat,
                                const int* __restrict__ offs,
                                const int* __restrict__ csr,
                                float* __restrict__ out, int N) {
    int t = blockIdx.x * blockDim.x + threadIdx.x;
    int node = t >> 4;
    int lane = threadIdx.x & 15;
    if (node >= N) return;
    int s = offs[node], e = offs[node + 1];
    const float4* f4 = (const float4*)feat;
    float4 acc = f4[(long long)node * 16 + lane];
    int k = s;
    for (; k + 7 < e; k += 8) {
        int j[8];
#pragma unroll
        for (int u = 0; u < 8; ++u) j[u] = __ldg(&csr[k + u]);
        float4 v[8];
#pragma unroll
        for (int u = 0; u < 8; ++u) v[u] = f4[(long long)j[u] * 16 + lane];
#pragma unroll
        for (int u = 0; u < 8; ++u) {
            acc.x += v[u].x; acc.y += v[u].y; acc.z += v[u].z; acc.w += v[u].w;
        }
    }
    for (; k < e; ++k) {
        int j = __ldg(&csr[k]);
        float4 v = f4[(long long)j * 16 + lane];
        acc.x += v.x; acc.y += v.y; acc.z += v.z; acc.w += v.w;
    }
    ((float4*)out)[(long long)node * 16 + lane] = acc;
}
__global__ void gather128_kernel(const float* __restrict__ feat,
                                 const int* __restrict__ offs,
                                 const int* __restrict__ csr,
                                 float* __restrict__ out, int N) {
    int node = (int)((blockIdx.x * blockDim.x + threadIdx.x) >> 5);
    int lane = threadIdx.x & 31;
    if (node >= N) return;
    int s = offs[node], e = offs[node + 1];
    const float4* f4 = (const float4*)feat;
    float4 acc = f4[(long long)node * 32 + lane];
    int k = s;
    for (; k + 7 < e; k += 8) {
        int j[8];
#pragma unroll
        for (int u = 0; u < 8; ++u) j[u] = __ldg(&csr[k + u]);
        float4 v[8];
#pragma unroll
        for (int u = 0; u < 8; ++u) v[u] = f4[(long long)j[u] * 32 + lane];
#pragma unroll
        for (int u = 0; u < 8; ++u) {
            acc.x += v[u].x; acc.y += v[u].y; acc.z += v[u].z; acc.w += v[u].w;
        }
    }
    for (; k < e; ++k) {
        int j = __ldg(&csr[k]);
        float4 v = f4[(long long)j * 32 + lane];
        acc.x += v.x; acc.y += v.y; acc.z += v.z; acc.w += v.w;
    }
    ((float4*)out)[(long long)node * 32 + lane] = acc;
}

// ======================= fused 2-GEMM MLP ==================================
// Out[N,CO2] = act2(relu(A[N,CI] @ W1[CI,128] + b1) @ W2[128,CO2] + b2)
// Unsplatted k-major tiles (stride 68); register splat via mov.b64 (idle
// slots — FMA2 rt binds). BK=32 W double buffer. 66KB smem -> 3 CTAs/SM.
template <int CI, int CO2, int RELU2>
__global__ void __launch_bounds__(256, 3)
mlp_fused_kernel(const float* __restrict__ A,
                 const float* __restrict__ W1, const float* __restrict__ b1,
                 const float* __restrict__ W2, const float* __restrict__ b2,
                 float* __restrict__ Out, int Nrows) {
    constexpr int SA  = 68;
    constexpr int KB1 = CI / 32;
    constexpr int KB2 = 128 / 32;
    constexpr int NG  = CO2 / 64;

    extern __shared__ float sm[];
    float* As = sm;                    // CI x SA   (aliases T1)
    float* T1 = sm;                    // 128 x SA
    float* Wb = sm + 128 * SA;         // 2 x 32 x 128 W double buffer
    const uint32_t wb_addr = smem_u32(Wb);
    constexpr uint32_t WBUF_BYTES = 32 * 128 * 4;

    const int tid = threadIdx.x;
    const int tr  = tid >> 4;
    const int tc  = tid & 15;
    const long long rowBase = (long long)blockIdx.x * 64;

    prefetch_w<128>(wb_addr, W1, 0, tid);

    constexpr int QA = CI / 4;
#pragma unroll
    for (int t = 0; t < 64 * QA / 256; ++t) {
        int idx = tid + t * 256;
        int m = idx / QA, q = idx % QA;
        long long row = rowBase + m;
        float4 v = make_float4(0.f, 0.f, 0.f, 0.f);
        if (row < Nrows) v = ((const float4*)(A + row * CI))[q];
        As[(q * 4 + 0) * SA + m] = v.x;
        As[(q * 4 + 1) * SA + m] = v.y;
        As[(q * 4 + 2) * SA + m] = v.z;
        As[(q * 4 + 3) * SA + m] = v.w;
    }
    if (KB1 > 1) prefetch_w<128>(wb_addr + WBUF_BYTES, W1, 1, tid);

    unsigned long long acc[4][4];
#pragma unroll
    for (int i = 0; i < 4; ++i)
#pragma unroll
        for (int j = 0; j < 4; ++j) acc[i][j] = 0ull;

    // ---------------- stage 1: acc = A @ W1 ----------------
#pragma unroll
    for (int kb = 0; kb < KB1; ++kb) {
        if (kb == KB1 - 1) { CP_WAIT0(); } else { CP_WAIT1(); }
        __syncthreads();
        const float* Bs  = Wb + (kb & 1) * (32 * 128);
        const float* Asb = As + kb * 32 * SA;
#pragma unroll
        for (int k = 0; k < 32; ++k) {
            float4 av = *(const float4*)&Asb[k * SA + tr * 4];
            unsigned long long ap0, ap1, ap2, ap3;
            PACK2(ap0, av.x); PACK2(ap1, av.y);
            PACK2(ap2, av.z); PACK2(ap3, av.w);
            ulonglong2 b0 = *(const ulonglong2*)&Bs[k * 128 + tc * 4];
            ulonglong2 b1v = *(const ulonglong2*)&Bs[k * 128 + 64 + tc * 4];
            FMA2(acc[0][0], ap0, b0.x); FMA2(acc[0][1], ap0, b0.y);
            FMA2(acc[0][2], ap0, b1v.x); FMA2(acc[0][3], ap0, b1v.y);
            FMA2(acc[1][0], ap1, b0.x); FMA2(acc[1][1], ap1, b0.y);
            FMA2(acc[1][2], ap1, b1v.x); FMA2(acc[1][3], ap1, b1v.y);
            FMA2(acc[2][0], ap2, b0.x); FMA2(acc[2][1], ap2, b0.y);
            FMA2(acc[2][2], ap2, b1v.x); FMA2(acc[2][3], ap2, b1v.y);
            FMA2(acc[3][0], ap3, b0.x); FMA2(acc[3][1], ap3, b0.y);
            FMA2(acc[3][2], ap3, b1v.x); FMA2(acc[3][3], ap3, b1v.y);
        }
        __syncthreads();
        if (kb + 2 < KB1) prefetch_w<128>(wb_addr + (kb & 1) * WBUF_BYTES, W1, kb + 2, tid);
    }

    prefetch_w<CO2>(wb_addr, W2, 0, tid);
    prefetch_w<CO2>(wb_addr + WBUF_BYTES, W2, 1, tid);

    // ---- stage-1 epilogue: bias + relu into T1 (aliasing As) ----
    {
        float bb[8];
#pragma unroll
        for (int e = 0; e < 4; ++e) {
            bb[e]     = __ldg(&b1[tc * 4 + e]);
            bb[4 + e] = __ldg(&b1[64 + tc * 4 + e]);
        }
#pragma unroll
        for (int i = 0; i < 4; ++i) {
            int m = tr * 4 + i;
#pragma unroll
            for (int g = 0; g < 2; ++g)
#pragma unroll
                for (int jp = 0; jp < 2; ++jp) {
                    uint32_t lo, hi;
                    UNPK(lo, hi, acc[i][g * 2 + jp]);
                    float v0 = fmaxf(__uint_as_float(lo) + bb[g * 4 + jp * 2 + 0], 0.f);
                    float v1 = fmaxf(__uint_as_float(hi) + bb[g * 4 + jp * 2 + 1], 0.f);
                    int c = g * 64 + tc * 4 + jp * 2;
                    T1[(c + 0) * SA + m] = v0;
                    T1[(c + 1) * SA + m] = v1;
                }
        }
    }
    __syncthreads();

    // ---------------- stage 2: out = T1 @ W2 ----------------
    unsigned long long acc2[4][2 * NG];
#pragma unroll
    for (int i = 0; i < 4; ++i)
#pragma unroll
        for (int j = 0; j < 2 * NG; ++j) acc2[i][j] = 0ull;

#pragma unroll
    for (int kb = 0; kb < KB2; ++kb) {
        if (kb == KB2 - 1) { CP_WAIT0(); } else { CP_WAIT1(); }
        __syncthreads();
        const float* Bs = Wb + (kb & 1) * (32 * 128);
        const float* Tb = T1 + kb * 32 * SA;
#pragma unroll
        for (int k = 0; k < 32; ++k) {
            float4 av = *(const float4*)&Tb[k * SA + tr * 4];
            unsigned long long ap0, ap1, ap2, ap3;
            PACK2(ap0, av.x); PACK2(ap1, av.y);
            PACK2(ap2, av.z); PACK2(ap3, av.w);
            ulonglong2 b0 = *(const ulonglong2*)&Bs[k * CO2 + tc * 4];
            FMA2(acc2[0][0], ap0, b0.x); FMA2(acc2[0][1], ap0, b0.y);
            FMA2(acc2[1][0], ap1, b0.x); FMA2(acc2[1][1], ap1, b0.y);
            FMA2(acc2[2][0], ap2, b0.x); FMA2(acc2[2][1], ap2, b0.y);
            FMA2(acc2[3][0], ap3, b0.x); FMA2(acc2[3][1], ap3, b0.y);
            if (NG == 2) {
                ulonglong2 b1v = *(const ulonglong2*)&Bs[k * CO2 + 64 + tc * 4];
                FMA2(acc2[0][2], ap0, b1v.x); FMA2(acc2[0][3], ap0, b1v.y);
                FMA2(acc2[1][2], ap1, b1v.x); FMA2(acc2[1][3], ap1, b1v.y);
                FMA2(acc2[2][2], ap2, b1v.x); FMA2(acc2[2][3], ap2, b1v.y);
                FMA2(acc2[3][2], ap3, b1v.x); FMA2(acc2[3][3], ap3, b1v.y);
            }
        }
        __syncthreads();
        if (kb + 2 < KB2) prefetch_w<CO2>(wb_addr + (kb & 1) * WBUF_BYTES, W2, kb + 2, tid);
    }

    // ---- final epilogue ----
    {
        float bb[4 * NG];
#pragma unroll
        for (int g = 0; g < NG; ++g)
#pragma unroll
            for (int e = 0; e < 4; ++e)
                bb[g * 4 + e] = __ldg(&b2[g * 64 + tc * 4 + e]);
#pragma unroll
        for (int i = 0; i < 4; ++i) {
            long long row = rowBase + tr * 4 + i;
            if (row >= Nrows) continue;
#pragma unroll
            for (int g = 0; g < NG; ++g) {
                uint32_t l0, h0, l1, h1;
                UNPK(l0, h0, acc2[i][g * 2 + 0]);
                UNPK(l1, h1, acc2[i][g * 2 + 1]);
                float4 o;
                o.x = __uint_as_float(l0) + bb[g * 4 + 0];
                o.y = __uint_as_float(h0) + bb[g * 4 + 1];
                o.z = __uint_as_float(l1) + bb[g * 4 + 2];
                o.w = __uint_as_float(h1) + bb[g * 4 + 3];
                if (RELU2) {
                    o.x = fmaxf(o.x, 0.f); o.y = fmaxf(o.y, 0.f);
                    o.z = fmaxf(o.z, 0.f); o.w = fmaxf(o.w, 0.f);
                }
                *(float4*)(Out + row * CO2 + g * 64 + tc * 4) = o;
            }
        }
    }
}

// ---------------------------------------------------------------------------
extern "C" void kernel_launch(void* const* d_in, const int* in_sizes, int n_in,
                              void* d_out, int out_size) {
    const float* x  = (const float*)d_in[0];
    const void*  ei = d_in[1];
    const float* W1 = (const float*)d_in[2];
    const float* b1 = (const float*)d_in[3];
    const float* W2 = (const float*)d_in[4];
    const float* b2 = (const float*)d_in[5];
    const float* W3 = (const float*)d_in[6];
    const float* b3 = (const float*)d_in[7];
    const float* W4 = (const float*)d_in[8];
    const float* b4 = (const float*)d_in[9];

    const int N = in_sizes[0] / CIN;
    const int E = in_sizes[1] / 2;

    float *h1pre, *h, *h2pre;
    cudaGetSymbolAddress((void**)&h1pre, g_h1pre);
    cudaGetSymbolAddress((void**)&h,     g_h);
    cudaGetSymbolAddress((void**)&h2pre, g_h2pre);
    int *deg, *offs, *csr, *rank;
    cudaGetSymbolAddress((void**)&deg,  g_deg);
    cudaGetSymbolAddress((void**)&offs, g_offs);
    cudaGetSymbolAddress((void**)&csr,  g_csr);
    cudaGetSymbolAddress((void**)&rank, g_rank);

    float* out = (float*)d_out;
    const int rtiles      = (N + 63) / 64;
    const int edge_blocks = (E + 255) / 256;
    const int scan_blocks = (N + SCAN_BS - 1) / SCAN_BS;   // 49 (< 148 SMs)
    const int g64_blocks  = (N * 16 + 255) / 256;
    const int g128_blocks = (N * 32 + 255) / 256;

    // Unsplatted As/T1 (128 x 68 floats) + BK=32 W double buffer -> 66KB.
    const int smem_mlp = (128 * 68 + 2 * 32 * 128) * 4;
    cudaFuncSetAttribute(mlp_fused_kernel<CIN,  CHID, 1>,
                         cudaFuncAttributeMaxDynamicSharedMemorySize, smem_mlp);
    cudaFuncSetAttribute(mlp_fused_kernel<CHID, CIN,  0>,
                         cudaFuncAttributeMaxDynamicSharedMemorySize, smem_mlp);

    // ---- CSR build (4 launches) ----
    detect_zero_kernel<<<(N + 255) / 256, 256>>>((const unsigned*)ei, deg, N);
    hist_kernel<<<edge_blocks, 256>>>(ei, deg, rank, E);
    scan_lookback_kernel<<<scan_blocks, SCAN_BS>>>(deg, offs, N);
    fill_kernel<<<edge_blocks, 256>>>(ei, offs, rank, csr, E);

    // ---- Layer 1 ----
    gather64_kernel<<<g64_blocks, 256>>>(x, offs, csr, h1pre, N);
    mlp_fused_kernel<CIN,  CHID, 1><<<rtiles, 256, smem_mlp>>>(h1pre, W1, b1, W2, b2, h, N);

    // ---- Layer 2 ----
    gather128_kernel<<<g128_blocks, 256>>>(h, offs, csr, h2pre, N);
    mlp_fused_kernel<CHID, CIN,  0><<<rtiles, 256, smem_mlp>>>(h2pre, W3, b3, W4, b4, out, N);
}